// round 11
// baseline (speedup 1.0000x reference)
#include <cuda_runtime.h>
#include <cuda_fp16.h>
#include <math.h>

#define NN 50000
#define NE 800000
#define NG 64
#define SCAN_B ((NN + 255) / 256)
#define TM ((NN + 127) / 128)   // 391 m-tiles

typedef unsigned long long u64;
typedef unsigned int u32;

// ---------------- scratch (device globals; no allocation allowed) -------------
__device__ __half g_act0[(size_t)NN * 256];   // activation ping
__device__ __half g_act1[(size_t)NN * 256];   // activation pong
__device__ float g_dinv[NN];
__device__ int   g_cnt[NN];
__device__ int   g_off[NN + 1];
__device__ int   g_cur[NN];
__device__ int   g_bsum[SCAN_B];
__device__ int   g_csr_src[NE];
__device__ float g_csr_norm[NE];
__device__ float g_pool[NG * 256];
// fp16 hi/lo weights per layer (0:W2 K=128, 1:W3, 2:W4)
__device__ unsigned short g_Wh[3][256 * 256];
__device__ unsigned short g_Wl[3][256 * 256];

__device__ __forceinline__ __half* actsel(int s) { return s ? g_act1 : g_act0; }

// ---------------- PTX helpers ---------------------------------------------------

__device__ __forceinline__ u32 smem_u32(const void* p) {
    u32 a;
    asm("{ .reg .u64 t; cvta.to.shared.u64 t, %1; cvt.u32.u64 %0, t; }" : "=r"(a) : "l"(p));
    return a;
}
__device__ __forceinline__ void ldmx4(u32* r, u32 a) {
    asm volatile("ldmatrix.sync.aligned.m8n8.x4.shared.b16 {%0,%1,%2,%3}, [%4];"
                 : "=r"(r[0]), "=r"(r[1]), "=r"(r[2]), "=r"(r[3]) : "r"(a));
}
__device__ __forceinline__ void ldmx4t(u32* r, u32 a) {
    asm volatile("ldmatrix.sync.aligned.m8n8.x4.trans.shared.b16 {%0,%1,%2,%3}, [%4];"
                 : "=r"(r[0]), "=r"(r[1]), "=r"(r[2]), "=r"(r[3]) : "r"(a));
}
__device__ __forceinline__ void mma16816h(float* c, const u32* a, const u32* b) {
    asm volatile(
        "mma.sync.aligned.m16n8k16.row.col.f32.f16.f16.f32 "
        "{%0,%1,%2,%3}, {%4,%5,%6,%7}, {%8,%9}, {%0,%1,%2,%3};"
        : "+f"(c[0]), "+f"(c[1]), "+f"(c[2]), "+f"(c[3])
        : "r"(a[0]), "r"(a[1]), "r"(a[2]), "r"(a[3]), "r"(b[0]), "r"(b[1]));
}
__device__ __forceinline__ void cp16(u32 dst, const void* src) {
    asm volatile("cp.async.cg.shared.global [%0], [%1], 16;"
                 :: "r"(dst), "l"(src) : "memory");
}
__device__ __forceinline__ void cp_commit() {
    asm volatile("cp.async.commit_group;" ::: "memory");
}
template <int N>
__device__ __forceinline__ void cp_wait() {
    asm volatile("cp.async.wait_group %0;" :: "n"(N) : "memory");
}

// ---------------- preprocessing ----------------------------------------------

__global__ void count_kernel(const int* __restrict__ dst) {
    int e = blockIdx.x * blockDim.x + threadIdx.x;
    if (e < NE) atomicAdd(&g_cnt[dst[e]], 1);
}

__global__ void scan1_kernel() {
    __shared__ int s[256];
    int tid = threadIdx.x;
    int idx = blockIdx.x * 256 + tid;
    int v = (idx < NN) ? g_cnt[idx] : 0;
    s[tid] = v;
    __syncthreads();
#pragma unroll
    for (int o = 1; o < 256; o <<= 1) {
        int t = (tid >= o) ? s[tid - o] : 0;
        __syncthreads();
        s[tid] += t;
        __syncthreads();
    }
    if (idx < NN) g_off[idx] = s[tid] - v;
    if (tid == 255) g_bsum[blockIdx.x] = s[255];
}

__global__ void scan2_kernel() {
    __shared__ int s[256];
    int tid = threadIdx.x;
    int v = (tid < SCAN_B) ? g_bsum[tid] : 0;
    s[tid] = v;
    __syncthreads();
#pragma unroll
    for (int o = 1; o < 256; o <<= 1) {
        int t = (tid >= o) ? s[tid - o] : 0;
        __syncthreads();
        s[tid] += t;
        __syncthreads();
    }
    if (tid < SCAN_B) g_bsum[tid] = s[tid] - v;
}

__global__ void finalize_kernel() {
    int v = blockIdx.x * blockDim.x + threadIdx.x;
    if (v < NN) {
        int off = g_off[v] + g_bsum[v >> 8];
        g_off[v] = off;
        g_cur[v] = off;
        g_dinv[v] = rsqrtf((float)g_cnt[v] + 1.0f);
    }
    if (v < NG * 256) g_pool[v] = -INFINITY;   // fused pool init
    if (v == 0) g_off[NN] = NE;
}

__global__ void fill_kernel(const int* __restrict__ src,
                            const int* __restrict__ dst) {
    int e = blockIdx.x * blockDim.x + threadIdx.x;
    if (e < NE) {
        int s = src[e];
        int d = dst[e];
        int pos = atomicAdd(&g_cur[d], 1);
        g_csr_src[pos] = s;
        g_csr_norm[pos] = g_dinv[s] * g_dinv[d];
    }
}

// ---------------- weight conversion (fp16 hi/lo) + zero counters ----------------

__global__ void conv_w_all(const float* __restrict__ W2,
                           const float* __restrict__ W3,
                           const float* __restrict__ W4) {
    int i = blockIdx.x * 256 + threadIdx.x;
    if (i < NN) g_cnt[i] = 0;   // fused zero_cnt
    const float* W;
    unsigned short *dh, *dl;
    int off;
    if (i < 32768)       { W = W2; off = i;           dh = g_Wh[0]; dl = g_Wl[0]; }
    else if (i < 98304)  { W = W3; off = i - 32768;   dh = g_Wh[1]; dl = g_Wl[1]; }
    else if (i < 163840) { W = W4; off = i - 98304;   dh = g_Wh[2]; dl = g_Wl[2]; }
    else return;
    float v = W[off];
    __half h = __float2half_rn(v);
    __half l = __float2half_rn(v - __half2float(h));
    dh[off] = __half_as_ushort(h);
    dl[off] = __half_as_ushort(l);
}

// ---------------- fused layer 1: agg9 + [N,9]@[9,128] + bias + relu -> act0 -----

__global__ __launch_bounds__(256) void layer1_kernel(const float* __restrict__ x,
                                                     const float* __restrict__ W1,
                                                     const float* __restrict__ b1) {
    __shared__ float Ws[9 * 128];
    __shared__ float Bs[128];
    int tid = threadIdx.x;
    for (int i = tid; i < 9 * 128; i += 256) Ws[i] = W1[i];
    if (tid < 128) Bs[tid] = b1[tid];
    __syncthreads();

    int warp = (blockIdx.x * 256 + tid) >> 5;
    int lane = tid & 31;
    if (warp >= NN) return;
    int v = warp;
    float dv = g_dinv[v];
    float acc = 0.f;
    if (lane < 9) acc = dv * dv * x[v * 9 + lane];
    int e0 = g_off[v], e1 = g_off[v + 1];
    for (int e = e0; e < e1; e++) {
        int s = g_csr_src[e];
        float nrm = g_csr_norm[e];
        if (lane < 9) acc += nrm * x[s * 9 + lane];
    }
    float ak[9];
#pragma unroll
    for (int k = 0; k < 9; k++) ak[k] = __shfl_sync(0xffffffffu, acc, k);

    int f = lane * 4;
    float o0 = Bs[f], o1 = Bs[f + 1], o2 = Bs[f + 2], o3 = Bs[f + 3];
#pragma unroll
    for (int k = 0; k < 9; k++) {
        float a = ak[k];
        const float* wr = &Ws[k * 128 + f];
        o0 += a * wr[0]; o1 += a * wr[1]; o2 += a * wr[2]; o3 += a * wr[3];
    }
    o0 = fmaxf(o0, 0.f); o1 = fmaxf(o1, 0.f);
    o2 = fmaxf(o2, 0.f); o3 = fmaxf(o3, 0.f);
    __half2* dst = (__half2*)(g_act0 + (size_t)v * 128 + f);
    dst[0] = __floats2half2_rn(o0, o1);
    dst[1] = __floats2half2_rn(o2, o3);
}

// ---------------- fused agg + GEMM layer -----------------------------------------
// Phase 1: warp-per-node aggregation of this block's 128 rows -> fp16 smem A
// Phase 2: [128,K] @ [K,256] fp16 2-pass (Whi + Wlo), B cp.async double-buffered

#define SB 136
#define B_ST (32 * SB)   // shorts per B stage (one of hi/lo)

template <int K, bool RELU>
__global__ __launch_bounds__(256) void fused_layer(const float* __restrict__ bias,
                                                   int wl, int selIn, int selOut) {
    extern __shared__ unsigned short smem[];
    const int SAE = K + 8;                       // A row stride (shorts)
    unsigned short* As = smem;                   // [128][SAE]
    unsigned short* Bh = As + 128 * SAE;         // [2][B_ST]
    unsigned short* Bl = Bh + 2 * B_ST;          // [2][B_ST]
    __shared__ float bs[256];

    const unsigned short* GWh = g_Wh[wl];
    const unsigned short* GWl = g_Wl[wl];
    const __half* In = actsel(selIn);
    __half* Out = actsel(selOut);

    int tid = threadIdx.x, lane = tid & 31, wid = tid >> 5;
    int tm = blockIdx.x;
    bs[tid] = bias[tid];

    u32 sAs = smem_u32(As), sBh = smem_u32(Bh), sBl = smem_u32(Bl);

    // B tile issue: stage st, K offset k0, N half tn
    auto issueB = [&](int st, int k0, int tn) {
#pragma unroll
        for (int i = 0; i < 2; i++) {
            int idx = tid + i * 256;
            int row = idx >> 4, cg = idx & 15;
            size_t gof = (size_t)(k0 + row) * 256 + tn * 128 + cg * 8;
            u32 dof = (u32)((st * B_ST + row * SB + cg * 8) * 2);
            cp16(sBh + dof, GWh + gof);
            cp16(sBl + dof, GWl + gof);
        }
        cp_commit();
    };
    issueB(0, 0, 0);   // prefetch first B tile; lands during phase 1

    // ---- phase 1: aggregate 16 nodes per warp into As ----
    for (int i = 0; i < 16; i++) {
        int row = wid * 16 + i;
        int v = tm * 128 + row;
        if (K == 256) {
            uint4 o = make_uint4(0, 0, 0, 0);
            if (v < NN) {
                float acc[8];
                float dv = g_dinv[v];
                float w = dv * dv;
                uint4 q = ((const uint4*)In)[(size_t)v * 32 + lane];
                __half2* h = (__half2*)&q;
#pragma unroll
                for (int j = 0; j < 4; j++) {
                    float2 f2 = __half22float2(h[j]);
                    acc[2 * j] = w * f2.x; acc[2 * j + 1] = w * f2.y;
                }
                int e0 = g_off[v], e1 = g_off[v + 1];
                int e = e0;
                for (; e + 4 <= e1; e += 4) {
                    int s0 = g_csr_src[e],     s1 = g_csr_src[e + 1];
                    int s2 = g_csr_src[e + 2], s3 = g_csr_src[e + 3];
                    float n0 = g_csr_norm[e],     n1 = g_csr_norm[e + 1];
                    float n2 = g_csr_norm[e + 2], n3 = g_csr_norm[e + 3];
                    uint4 q0 = ((const uint4*)In)[(size_t)s0 * 32 + lane];
                    uint4 q1 = ((const uint4*)In)[(size_t)s1 * 32 + lane];
                    uint4 q2 = ((const uint4*)In)[(size_t)s2 * 32 + lane];
                    uint4 q3 = ((const uint4*)In)[(size_t)s3 * 32 + lane];
                    __half2 *h0 = (__half2*)&q0, *h1 = (__half2*)&q1;
                    __half2 *h2 = (__half2*)&q2, *h3 = (__half2*)&q3;
#pragma unroll
                    for (int j = 0; j < 4; j++) {
                        float2 f0 = __half22float2(h0[j]), f1 = __half22float2(h1[j]);
                        float2 f2 = __half22float2(h2[j]), f3 = __half22float2(h3[j]);
                        acc[2 * j]     += n0 * f0.x + n1 * f1.x + n2 * f2.x + n3 * f3.x;
                        acc[2 * j + 1] += n0 * f0.y + n1 * f1.y + n2 * f2.y + n3 * f3.y;
                    }
                }
                for (; e < e1; e++) {
                    int s = g_csr_src[e];
                    float nrm = g_csr_norm[e];
                    uint4 q0 = ((const uint4*)In)[(size_t)s * 32 + lane];
                    __half2* h0 = (__half2*)&q0;
#pragma unroll
                    for (int j = 0; j < 4; j++) {
                        float2 f2 = __half22float2(h0[j]);
                        acc[2 * j] += nrm * f2.x; acc[2 * j + 1] += nrm * f2.y;
                    }
                }
                __half2* ho = (__half2*)&o;
#pragma unroll
                for (int j = 0; j < 4; j++)
                    ho[j] = __floats2half2_rn(acc[2 * j], acc[2 * j + 1]);
            }
            *(uint4*)(As + row * SAE + lane * 8) = o;
        } else {
            uint2 o = make_uint2(0, 0);
            if (v < NN) {
                float acc[4];
                float dv = g_dinv[v];
                float w = dv * dv;
                uint2 q = ((const uint2*)In)[(size_t)v * 32 + lane];
                __half2* h = (__half2*)&q;
#pragma unroll
                for (int j = 0; j < 2; j++) {
                    float2 f2 = __half22float2(h[j]);
                    acc[2 * j] = w * f2.x; acc[2 * j + 1] = w * f2.y;
                }
                int e0 = g_off[v], e1 = g_off[v + 1];
                int e = e0;
                for (; e + 4 <= e1; e += 4) {
                    int s0 = g_csr_src[e],     s1 = g_csr_src[e + 1];
                    int s2 = g_csr_src[e + 2], s3 = g_csr_src[e + 3];
                    float n0 = g_csr_norm[e],     n1 = g_csr_norm[e + 1];
                    float n2 = g_csr_norm[e + 2], n3 = g_csr_norm[e + 3];
                    uint2 q0 = ((const uint2*)In)[(size_t)s0 * 32 + lane];
                    uint2 q1 = ((const uint2*)In)[(size_t)s1 * 32 + lane];
                    uint2 q2 = ((const uint2*)In)[(size_t)s2 * 32 + lane];
                    uint2 q3 = ((const uint2*)In)[(size_t)s3 * 32 + lane];
                    __half2 *h0 = (__half2*)&q0, *h1 = (__half2*)&q1;
                    __half2 *h2 = (__half2*)&q2, *h3 = (__half2*)&q3;
#pragma unroll
                    for (int j = 0; j < 2; j++) {
                        float2 f0 = __half22float2(h0[j]), f1 = __half22float2(h1[j]);
                        float2 f2 = __half22float2(h2[j]), f3 = __half22float2(h3[j]);
                        acc[2 * j]     += n0 * f0.x + n1 * f1.x + n2 * f2.x + n3 * f3.x;
                        acc[2 * j + 1] += n0 * f0.y + n1 * f1.y + n2 * f2.y + n3 * f3.y;
                    }
                }
                for (; e < e1; e++) {
                    int s = g_csr_src[e];
                    float nrm = g_csr_norm[e];
                    uint2 q0 = ((const uint2*)In)[(size_t)s * 32 + lane];
                    __half2* h0 = (__half2*)&q0;
#pragma unroll
                    for (int j = 0; j < 2; j++) {
                        float2 f2 = __half22float2(h0[j]);
                        acc[2 * j] += nrm * f2.x; acc[2 * j + 1] += nrm * f2.y;
                    }
                }
                __half2* ho = (__half2*)&o;
#pragma unroll
                for (int j = 0; j < 2; j++)
                    ho[j] = __floats2half2_rn(acc[2 * j], acc[2 * j + 1]);
            }
            *(uint2*)(As + row * SAE + lane * 4) = o;
        }
    }
    __syncthreads();

    // ---- phase 2: GEMM, two N halves reusing smem A ----
    int wm = wid & 3, wn = wid >> 2;
    const int niter = K >> 5;
    for (int tn = 0; tn < 2; tn++) {
        float c[16][4];
#pragma unroll
        for (int i = 0; i < 16; i++)
#pragma unroll
            for (int j = 0; j < 4; j++) c[i][j] = 0.f;

        if (tn == 1) issueB(0, 0, 1);
        for (int it = 0; it < niter; it++) {
            int cur = it & 1;
            if (it + 1 < niter) {
                issueB((it + 1) & 1, (it + 1) << 5, tn);
                cp_wait<1>();
            } else {
                cp_wait<0>();
            }
            __syncthreads();
            int k0 = it << 5;
            u32 bof = (u32)(cur * B_ST * 2);
#pragma unroll
            for (int ks = 0; ks < 2; ks++) {
                u32 ah[2][4], bh[4][4], bl[4][4];
                int ar = wm * 32 + (lane & 15);
                int ac = k0 + ks * 16 + (lane >> 4) * 8;
                ldmx4(ah[0], sAs + (u32)((ar * SAE + ac) * 2));
                ldmx4(ah[1], sAs + (u32)(((ar + 16) * SAE + ac) * 2));
                int br = ks * 16 + (lane & 15);
#pragma unroll
                for (int g = 0; g < 4; g++) {
                    int bc = wn * 64 + g * 16 + (lane >> 4) * 8;
                    ldmx4t(bh[g], sBh + bof + (u32)((br * SB + bc) * 2));
                    ldmx4t(bl[g], sBl + bof + (u32)((br * SB + bc) * 2));
                }
#pragma unroll
                for (int mt = 0; mt < 2; mt++)
#pragma unroll
                    for (int nt = 0; nt < 8; nt++) {
                        float* cc = c[mt * 8 + nt];
                        const u32* pbh = &bh[nt >> 1][(nt & 1) * 2];
                        const u32* pbl = &bl[nt >> 1][(nt & 1) * 2];
                        mma16816h(cc, ah[mt], pbh);
                        mma16816h(cc, ah[mt], pbl);
                    }
            }
            __syncthreads();
        }

        // epilogue for this N half: bias + optional relu -> fp16 Out [NN][256]
#pragma unroll
        for (int mt = 0; mt < 2; mt++) {
#pragma unroll
            for (int nt = 0; nt < 8; nt++) {
                int r0 = tm * 128 + wm * 32 + mt * 16 + (lane >> 2);
                int cl = wn * 64 + nt * 8 + (lane & 3) * 2;
                int col = tn * 128 + cl;
                float b0 = bs[col], b1 = bs[col + 1];
                float v0 = c[mt * 8 + nt][0] + b0;
                float v1 = c[mt * 8 + nt][1] + b1;
                float v2 = c[mt * 8 + nt][2] + b0;
                float v3 = c[mt * 8 + nt][3] + b1;
                if (RELU) {
                    v0 = fmaxf(v0, 0.f); v1 = fmaxf(v1, 0.f);
                    v2 = fmaxf(v2, 0.f); v3 = fmaxf(v3, 0.f);
                }
                if (r0 < NN)
                    *(__half2*)(Out + (size_t)r0 * 256 + col) = __floats2half2_rn(v0, v1);
                if (r0 + 8 < NN)
                    *(__half2*)(Out + (size_t)(r0 + 8) * 256 + col) = __floats2half2_rn(v2, v3);
            }
        }
    }
}

// ---------------- global max pool ----------------------------------------------

__device__ __forceinline__ void atomicMaxF(float* a, float v) {
    if (v >= 0.f) atomicMax((int*)a, __float_as_int(v));
    else          atomicMin((unsigned int*)a, __float_as_uint(v));
}

__global__ __launch_bounds__(256) void pool_kernel(const int* __restrict__ batch, int sel) {
    const __half* H = actsel(sel);
    int f = threadIdx.x;
    int v0 = blockIdx.x * 64;
    int vend = min(v0 + 64, NN);
    if (v0 >= NN) return;
    float m = -INFINITY;
    int cg = batch[v0];
    for (int v = v0; v < vend; v++) {
        int g = batch[v];
        if (g != cg) {
            atomicMaxF(&g_pool[cg * 256 + f], m);
            m = -INFINITY;
            cg = g;
        }
        m = fmaxf(m, __half2float(H[(size_t)v * 256 + f]));
    }
    atomicMaxF(&g_pool[cg * 256 + f], m);
}

// ---------------- dense head ----------------------------------------------------

__global__ __launch_bounds__(128) void head_kernel(const float* __restrict__ Wl2,
                                                   const float* __restrict__ bl2,
                                                   const float* __restrict__ Wl3,
                                                   const float* __restrict__ bl3,
                                                   const float* __restrict__ Wl,
                                                   const float* __restrict__ bl,
                                                   float* __restrict__ out) {
    __shared__ float gs[256];
    __shared__ float h2[128];
    __shared__ float h3[128];
    int g = blockIdx.x;
    int t = threadIdx.x;
    gs[t]       = g_pool[g * 256 + t];
    gs[t + 128] = g_pool[g * 256 + 128 + t];
    __syncthreads();
    float a = bl2[t];
    for (int k = 0; k < 256; k++) a += gs[k] * Wl2[k * 128 + t];
    h2[t] = fmaxf(a, 0.f);
    __syncthreads();
    float b = bl3[t];
    for (int k = 0; k < 128; k++) b += h2[k] * Wl3[k * 128 + t];
    h3[t] = fmaxf(b, 0.f);
    __syncthreads();
    if (t < 10) {
        float c = bl[t];
        for (int k = 0; k < 128; k++) c += h3[k] * Wl[k * 10 + t];
        out[g * 10 + t] = c;
    }
}

// ---------------- launch ---------------------------------------------------------

#define FL_SMEM(K) ((128 * ((K) + 8) + 4 * B_ST) * 2)

extern "C" void kernel_launch(void* const* d_in, const int* in_sizes, int n_in,
                              void* d_out, int out_size) {
    const float* x     = (const float*)d_in[0];
    const int*   ei    = (const int*)d_in[1];
    const int*   batch = (const int*)d_in[2];
    const float *W1 = (const float*)d_in[3],  *b1 = (const float*)d_in[4];
    const float *W2 = (const float*)d_in[5],  *b2 = (const float*)d_in[6];
    const float *W3 = (const float*)d_in[7],  *b3 = (const float*)d_in[8];
    const float *W4 = (const float*)d_in[9],  *b4 = (const float*)d_in[10];
    const float *Wl2 = (const float*)d_in[11], *bl2 = (const float*)d_in[12];
    const float *Wl3 = (const float*)d_in[13], *bl3 = (const float*)d_in[14];
    const float *Wl  = (const float*)d_in[15], *bl  = (const float*)d_in[16];
    float* out = (float*)d_out;

    const int* esrc = ei;
    const int* edst = ei + NE;

    cudaFuncSetAttribute(fused_layer<128, true>,
                         cudaFuncAttributeMaxDynamicSharedMemorySize, FL_SMEM(128));
    cudaFuncSetAttribute(fused_layer<256, true>,
                         cudaFuncAttributeMaxDynamicSharedMemorySize, FL_SMEM(256));
    cudaFuncSetAttribute(fused_layer<256, false>,
                         cudaFuncAttributeMaxDynamicSharedMemorySize, FL_SMEM(256));

    // preprocessing (conv_w_all also zeroes g_cnt)
    conv_w_all<<<(163840 + 255) / 256, 256>>>(W2, W3, W4);
    count_kernel<<<(NE + 255) / 256, 256>>>(edst);
    scan1_kernel<<<SCAN_B, 256>>>();
    scan2_kernel<<<1, 256>>>();
    finalize_kernel<<<(NN + 255) / 256, 256>>>();
    fill_kernel<<<(NE + 255) / 256, 256>>>(esrc, edst);

    // layer 1: fused agg9 + GEMM(9->128) + relu -> act0 (stride 128)
    layer1_kernel<<<(NN + 7) / 8, 256>>>(x, W1, b1);

    // layers 2-4: fused aggregate+GEMM, ping-pong activation buffers
    fused_layer<128, true><<<TM, 256, FL_SMEM(128)>>>(b2, 0, 0, 1);   // act0 -> act1
    fused_layer<256, true><<<TM, 256, FL_SMEM(256)>>>(b3, 1, 1, 0);   // act1 -> act0
    fused_layer<256, false><<<TM, 256, FL_SMEM(256)>>>(b4, 2, 0, 1);  // act0 -> act1

    // pool + head (reads act1)
    pool_kernel<<<(NN + 63) / 64, 256>>>(batch, 1);
    head_kernel<<<NG, 128>>>(Wl2, bl2, Wl3, bl3, Wl, bl, out);
}

// round 12
// speedup vs baseline: 1.6196x; 1.6196x over previous
#include <cuda_runtime.h>
#include <cuda_fp16.h>
#include <math.h>

#define NN 50000
#define NE 800000
#define NG 64
#define SCAN_B ((NN + 255) / 256)
#define TM ((NN + 127) / 128)   // 391 m-tiles

typedef unsigned long long u64;
typedef unsigned int u32;

// ---------------- scratch (device globals; no allocation allowed) -------------
__device__ __half g_h16[(size_t)NN * 256];   // layer activations, fp16
__device__ __half g_A16[(size_t)NN * 256];   // aggregated activations (GEMM A), fp16
__device__ float g_dinv[NN];
__device__ int   g_cnt[NN];
__device__ int   g_off[NN + 1];
__device__ int   g_cur[NN];
__device__ int   g_bsum[SCAN_B];
__device__ int   g_csr_src[NE];
__device__ float g_csr_norm[NE];
__device__ float g_pool[NG * 256];
// fp16 weights per layer (0:W2 K=128, 1:W3, 2:W4)
__device__ unsigned short g_Wh[3][256 * 256];

// ---------------- PTX helpers ---------------------------------------------------

__device__ __forceinline__ u32 smem_u32(const void* p) {
    u32 a;
    asm("{ .reg .u64 t; cvta.to.shared.u64 t, %1; cvt.u32.u64 %0, t; }" : "=r"(a) : "l"(p));
    return a;
}
__device__ __forceinline__ void ldmx4(u32* r, u32 a) {
    asm volatile("ldmatrix.sync.aligned.m8n8.x4.shared.b16 {%0,%1,%2,%3}, [%4];"
                 : "=r"(r[0]), "=r"(r[1]), "=r"(r[2]), "=r"(r[3]) : "r"(a));
}
__device__ __forceinline__ void ldmx4t(u32* r, u32 a) {
    asm volatile("ldmatrix.sync.aligned.m8n8.x4.trans.shared.b16 {%0,%1,%2,%3}, [%4];"
                 : "=r"(r[0]), "=r"(r[1]), "=r"(r[2]), "=r"(r[3]) : "r"(a));
}
__device__ __forceinline__ void mma16816h(float* c, const u32* a, const u32* b) {
    asm volatile(
        "mma.sync.aligned.m16n8k16.row.col.f32.f16.f16.f32 "
        "{%0,%1,%2,%3}, {%4,%5,%6,%7}, {%8,%9}, {%0,%1,%2,%3};"
        : "+f"(c[0]), "+f"(c[1]), "+f"(c[2]), "+f"(c[3])
        : "r"(a[0]), "r"(a[1]), "r"(a[2]), "r"(a[3]), "r"(b[0]), "r"(b[1]));
}
__device__ __forceinline__ void cp16(u32 dst, const void* src, u32 sz) {
    asm volatile("cp.async.cg.shared.global [%0], [%1], 16, %2;"
                 :: "r"(dst), "l"(src), "r"(sz) : "memory");
}
__device__ __forceinline__ void cp_commit() {
    asm volatile("cp.async.commit_group;" ::: "memory");
}
template <int N>
__device__ __forceinline__ void cp_wait() {
    asm volatile("cp.async.wait_group %0;" :: "n"(N) : "memory");
}

// ---------------- preprocessing ----------------------------------------------

__global__ void count_kernel(const int* __restrict__ dst) {
    int e = blockIdx.x * blockDim.x + threadIdx.x;
    if (e < NE) atomicAdd(&g_cnt[dst[e]], 1);
}

__global__ void scan1_kernel() {
    __shared__ int s[256];
    int tid = threadIdx.x;
    int idx = blockIdx.x * 256 + tid;
    int v = (idx < NN) ? g_cnt[idx] : 0;
    s[tid] = v;
    __syncthreads();
#pragma unroll
    for (int o = 1; o < 256; o <<= 1) {
        int t = (tid >= o) ? s[tid - o] : 0;
        __syncthreads();
        s[tid] += t;
        __syncthreads();
    }
    if (idx < NN) g_off[idx] = s[tid] - v;
    if (tid == 255) g_bsum[blockIdx.x] = s[255];
}

__global__ void scan2_kernel() {
    __shared__ int s[256];
    int tid = threadIdx.x;
    int v = (tid < SCAN_B) ? g_bsum[tid] : 0;
    s[tid] = v;
    __syncthreads();
#pragma unroll
    for (int o = 1; o < 256; o <<= 1) {
        int t = (tid >= o) ? s[tid - o] : 0;
        __syncthreads();
        s[tid] += t;
        __syncthreads();
    }
    if (tid < SCAN_B) g_bsum[tid] = s[tid] - v;
}

__global__ void finalize_kernel() {
    int v = blockIdx.x * blockDim.x + threadIdx.x;
    if (v < NN) {
        int off = g_off[v] + g_bsum[v >> 8];
        g_off[v] = off;
        g_cur[v] = off;
        g_dinv[v] = rsqrtf((float)g_cnt[v] + 1.0f);
    }
    if (v < NG * 256) g_pool[v] = -INFINITY;   // fused pool init
    if (v == 0) g_off[NN] = NE;
}

__global__ void fill_kernel(const int* __restrict__ src,
                            const int* __restrict__ dst) {
    int e = blockIdx.x * blockDim.x + threadIdx.x;
    if (e < NE) {
        int s = src[e];
        int d = dst[e];
        int pos = atomicAdd(&g_cur[d], 1);
        g_csr_src[pos] = s;
        g_csr_norm[pos] = g_dinv[s] * g_dinv[d];
    }
}

// ---------------- weight conversion (fp16) + zero counters ----------------------

__global__ void conv_w_all(const float* __restrict__ W2,
                           const float* __restrict__ W3,
                           const float* __restrict__ W4) {
    int i = blockIdx.x * 256 + threadIdx.x;
    if (i < NN) g_cnt[i] = 0;   // fused zero_cnt
    const float* W;
    unsigned short* dh;
    int off;
    if (i < 32768)       { W = W2; off = i;           dh = g_Wh[0]; }
    else if (i < 98304)  { W = W3; off = i - 32768;   dh = g_Wh[1]; }
    else if (i < 163840) { W = W4; off = i - 98304;   dh = g_Wh[2]; }
    else return;
    dh[off] = __half_as_ushort(__float2half_rn(W[off]));
}

// ---------------- fused layer 1: agg9 + [N,9]@[9,128] + bias + relu -> fp16 -----

__global__ __launch_bounds__(256) void layer1_kernel(const float* __restrict__ x,
                                                     const float* __restrict__ W1,
                                                     const float* __restrict__ b1) {
    __shared__ float Ws[9 * 128];
    __shared__ float Bs[128];
    int tid = threadIdx.x;
    for (int i = tid; i < 9 * 128; i += 256) Ws[i] = W1[i];
    if (tid < 128) Bs[tid] = b1[tid];
    __syncthreads();

    int warp = (blockIdx.x * 256 + tid) >> 5;
    int lane = tid & 31;
    if (warp >= NN) return;
    int v = warp;
    float dv = g_dinv[v];
    float acc = 0.f;
    if (lane < 9) acc = dv * dv * x[v * 9 + lane];
    int e0 = g_off[v], e1 = g_off[v + 1];
    for (int e = e0; e < e1; e++) {
        int s = g_csr_src[e];
        float nrm = g_csr_norm[e];
        if (lane < 9) acc += nrm * x[s * 9 + lane];
    }
    float ak[9];
#pragma unroll
    for (int k = 0; k < 9; k++) ak[k] = __shfl_sync(0xffffffffu, acc, k);

    int f = lane * 4;
    float o0 = Bs[f], o1 = Bs[f + 1], o2 = Bs[f + 2], o3 = Bs[f + 3];
#pragma unroll
    for (int k = 0; k < 9; k++) {
        float a = ak[k];
        const float* wr = &Ws[k * 128 + f];
        o0 += a * wr[0]; o1 += a * wr[1]; o2 += a * wr[2]; o3 += a * wr[3];
    }
    o0 = fmaxf(o0, 0.f); o1 = fmaxf(o1, 0.f);
    o2 = fmaxf(o2, 0.f); o3 = fmaxf(o3, 0.f);
    __half2* dst = (__half2*)(g_h16 + (size_t)v * 128 + f);
    dst[0] = __floats2half2_rn(o0, o1);
    dst[1] = __floats2half2_rn(o2, o3);
}

// ---------------- aggregation: gather fp16 rows -> fp16 A operand ---------------

template <int F>
__global__ __launch_bounds__(256) void agg_f16() {
    int warp = (blockIdx.x * blockDim.x + threadIdx.x) >> 5;
    int lane = threadIdx.x & 31;
    if (warp >= NN) return;
    const int v = warp;

    float acc[F / 32];
    float dv = g_dinv[v];
    float w = dv * dv;
    if (F == 256) {
        uint4 q = ((const uint4*)g_h16)[(size_t)v * 32 + lane];
        __half2* h = (__half2*)&q;
#pragma unroll
        for (int j = 0; j < 4; j++) {
            float2 f2 = __half22float2(h[j]);
            acc[2 * j] = w * f2.x; acc[2 * j + 1] = w * f2.y;
        }
    } else {
        uint2 q = ((const uint2*)g_h16)[(size_t)v * 32 + lane];
        __half2* h = (__half2*)&q;
#pragma unroll
        for (int j = 0; j < 2; j++) {
            float2 f2 = __half22float2(h[j]);
            acc[2 * j] = w * f2.x; acc[2 * j + 1] = w * f2.y;
        }
    }

    int e0 = g_off[v], e1 = g_off[v + 1];
    int e = e0;
    for (; e + 4 <= e1; e += 4) {
        int s0 = g_csr_src[e],     s1 = g_csr_src[e + 1];
        int s2 = g_csr_src[e + 2], s3 = g_csr_src[e + 3];
        float n0 = g_csr_norm[e],     n1 = g_csr_norm[e + 1];
        float n2 = g_csr_norm[e + 2], n3 = g_csr_norm[e + 3];
        if (F == 256) {
            uint4 q0 = ((const uint4*)g_h16)[(size_t)s0 * 32 + lane];
            uint4 q1 = ((const uint4*)g_h16)[(size_t)s1 * 32 + lane];
            uint4 q2 = ((const uint4*)g_h16)[(size_t)s2 * 32 + lane];
            uint4 q3 = ((const uint4*)g_h16)[(size_t)s3 * 32 + lane];
            __half2 *h0 = (__half2*)&q0, *h1 = (__half2*)&q1;
            __half2 *h2 = (__half2*)&q2, *h3 = (__half2*)&q3;
#pragma unroll
            for (int j = 0; j < 4; j++) {
                float2 f0 = __half22float2(h0[j]), f1 = __half22float2(h1[j]);
                float2 f2 = __half22float2(h2[j]), f3 = __half22float2(h3[j]);
                acc[2 * j]     += n0 * f0.x + n1 * f1.x + n2 * f2.x + n3 * f3.x;
                acc[2 * j + 1] += n0 * f0.y + n1 * f1.y + n2 * f2.y + n3 * f3.y;
            }
        } else {
            uint2 q0 = ((const uint2*)g_h16)[(size_t)s0 * 32 + lane];
            uint2 q1 = ((const uint2*)g_h16)[(size_t)s1 * 32 + lane];
            uint2 q2 = ((const uint2*)g_h16)[(size_t)s2 * 32 + lane];
            uint2 q3 = ((const uint2*)g_h16)[(size_t)s3 * 32 + lane];
            __half2 *h0 = (__half2*)&q0, *h1 = (__half2*)&q1;
            __half2 *h2 = (__half2*)&q2, *h3 = (__half2*)&q3;
#pragma unroll
            for (int j = 0; j < 2; j++) {
                float2 f0 = __half22float2(h0[j]), f1 = __half22float2(h1[j]);
                float2 f2 = __half22float2(h2[j]), f3 = __half22float2(h3[j]);
                acc[2 * j]     += n0 * f0.x + n1 * f1.x + n2 * f2.x + n3 * f3.x;
                acc[2 * j + 1] += n0 * f0.y + n1 * f1.y + n2 * f2.y + n3 * f3.y;
            }
        }
    }
    for (; e < e1; e++) {
        int s = g_csr_src[e];
        float nrm = g_csr_norm[e];
        if (F == 256) {
            uint4 q0 = ((const uint4*)g_h16)[(size_t)s * 32 + lane];
            __half2* h0 = (__half2*)&q0;
#pragma unroll
            for (int j = 0; j < 4; j++) {
                float2 f2 = __half22float2(h0[j]);
                acc[2 * j] += nrm * f2.x; acc[2 * j + 1] += nrm * f2.y;
            }
        } else {
            uint2 q0 = ((const uint2*)g_h16)[(size_t)s * 32 + lane];
            __half2* h0 = (__half2*)&q0;
#pragma unroll
            for (int j = 0; j < 2; j++) {
                float2 f2 = __half22float2(h0[j]);
                acc[2 * j] += nrm * f2.x; acc[2 * j + 1] += nrm * f2.y;
            }
        }
    }

    if (F == 256) {
        uint4 o;
        __half2* ho = (__half2*)&o;
#pragma unroll
        for (int j = 0; j < 4; j++) ho[j] = __floats2half2_rn(acc[2 * j], acc[2 * j + 1]);
        ((uint4*)g_A16)[(size_t)v * 32 + lane] = o;
    } else {
        uint2 o;
        __half2* ho = (__half2*)&o;
#pragma unroll
        for (int j = 0; j < 2; j++) ho[j] = __floats2half2_rn(acc[2 * j], acc[2 * j + 1]);
        ((uint2*)g_A16)[(size_t)v * 32 + lane] = o;
    }
}

// ---------------- mma.sync fp16 GEMM (single-pass W), cp.async double-buffered --
// BM=128, BN=128, BK=32; 8 warps (4x2), warp tile 32x64; output fp16 -> g_h16

#define SA 40
#define SB 136
#define A_ST (128 * SA)
#define B_ST (32 * SB)
#define GT_SMEM ((2 * A_ST + 2 * B_ST) * 2)

__global__ __launch_bounds__(256) void gemm_mma(const float* __restrict__ bias,
                                                int relu, int K, int wl) {
    extern __shared__ unsigned short smem[];
    unsigned short* Aa = smem;                  // [2][A_ST]
    unsigned short* Bh = Aa + 2 * A_ST;         // [2][B_ST]
    __shared__ float bs[128];

    const unsigned short* GWh = g_Wh[wl];

    int tid = threadIdx.x, lane = tid & 31, wid = tid >> 5;
    int tm = blockIdx.x, tn = blockIdx.y;
    int wm = wid & 3, wn = wid >> 2;
    if (tid < 128) bs[tid] = bias[tn * 128 + tid];

    float c[16][4];
#pragma unroll
    for (int i = 0; i < 16; i++)
#pragma unroll
        for (int j = 0; j < 4; j++) c[i][j] = 0.f;

    u32 sAa = smem_u32(Aa);
    u32 sBh = smem_u32(Bh);

    auto issue = [&](int st, int k0) {
#pragma unroll
        for (int i = 0; i < 2; i++) {
            int idx = tid + i * 256;
            int row = idx >> 2, cg = idx & 3;
            int grow = tm * 128 + row;
            u32 sz = (grow < NN) ? 16u : 0u;
            size_t gof = (size_t)grow * K + k0 + cg * 8;
            u32 dof = (u32)((st * A_ST + row * SA + cg * 8) * 2);
            cp16(sAa + dof, g_A16 + gof, sz);
        }
#pragma unroll
        for (int i = 0; i < 2; i++) {
            int idx = tid + i * 256;
            int row = idx >> 4, cg = idx & 15;
            size_t gof = (size_t)(k0 + row) * 256 + tn * 128 + cg * 8;
            u32 dof = (u32)((st * B_ST + row * SB + cg * 8) * 2);
            cp16(sBh + dof, GWh + gof, 16u);
        }
        cp_commit();
    };

    const int niter = K >> 5;
    issue(0, 0);
    for (int it = 0; it < niter; it++) {
        int cur = it & 1;
        if (it + 1 < niter) {
            issue((it + 1) & 1, (it + 1) << 5);
            cp_wait<1>();
        } else {
            cp_wait<0>();
        }
        __syncthreads();

        u32 aof = (u32)(cur * A_ST * 2), bof = (u32)(cur * B_ST * 2);
#pragma unroll
        for (int ks = 0; ks < 2; ks++) {
            u32 ah[2][4], bh[4][4];
            int ar = wm * 32 + (lane & 15);
            int ac = ks * 16 + (lane >> 4) * 8;
            ldmx4(ah[0], sAa + aof + (u32)((ar * SA + ac) * 2));
            ldmx4(ah[1], sAa + aof + (u32)(((ar + 16) * SA + ac) * 2));
            int br = ks * 16 + (lane & 15);
#pragma unroll
            for (int g = 0; g < 4; g++) {
                int bc = wn * 64 + g * 16 + (lane >> 4) * 8;
                ldmx4t(bh[g], sBh + bof + (u32)((br * SB + bc) * 2));
            }
#pragma unroll
            for (int mt = 0; mt < 2; mt++)
#pragma unroll
                for (int nt = 0; nt < 8; nt++) {
                    mma16816h(c[mt * 8 + nt], ah[mt], &bh[nt >> 1][(nt & 1) * 2]);
                }
        }
        __syncthreads();
    }

    // epilogue: bias + optional relu -> fp16 g_h16 [NN][256]
#pragma unroll
    for (int mt = 0; mt < 2; mt++) {
#pragma unroll
        for (int nt = 0; nt < 8; nt++) {
            int r0 = tm * 128 + wm * 32 + mt * 16 + (lane >> 2);
            int cl = wn * 64 + nt * 8 + (lane & 3) * 2;
            int col = tn * 128 + cl;
            float b0 = bs[cl], b1 = bs[cl + 1];
            float v0 = c[mt * 8 + nt][0] + b0;
            float v1 = c[mt * 8 + nt][1] + b1;
            float v2 = c[mt * 8 + nt][2] + b0;
            float v3 = c[mt * 8 + nt][3] + b1;
            if (relu) {
                v0 = fmaxf(v0, 0.f); v1 = fmaxf(v1, 0.f);
                v2 = fmaxf(v2, 0.f); v3 = fmaxf(v3, 0.f);
            }
            if (r0 < NN)
                *(__half2*)(g_h16 + (size_t)r0 * 256 + col) = __floats2half2_rn(v0, v1);
            if (r0 + 8 < NN)
                *(__half2*)(g_h16 + (size_t)(r0 + 8) * 256 + col) = __floats2half2_rn(v2, v3);
        }
    }
}

// ---------------- global max pool ----------------------------------------------

__device__ __forceinline__ void atomicMaxF(float* a, float v) {
    if (v >= 0.f) atomicMax((int*)a, __float_as_int(v));
    else          atomicMin((unsigned int*)a, __float_as_uint(v));
}

__global__ __launch_bounds__(256) void pool_kernel(const int* __restrict__ batch) {
    const __half* H = g_h16;
    int f = threadIdx.x;
    int v0 = blockIdx.x * 64;
    int vend = min(v0 + 64, NN);
    if (v0 >= NN) return;
    float m = -INFINITY;
    int cg = batch[v0];
    for (int v = v0; v < vend; v++) {
        int g = batch[v];
        if (g != cg) {
            atomicMaxF(&g_pool[cg * 256 + f], m);
            m = -INFINITY;
            cg = g;
        }
        m = fmaxf(m, __half2float(H[(size_t)v * 256 + f]));
    }
    atomicMaxF(&g_pool[cg * 256 + f], m);
}

// ---------------- dense head ----------------------------------------------------

__global__ __launch_bounds__(128) void head_kernel(const float* __restrict__ Wl2,
                                                   const float* __restrict__ bl2,
                                                   const float* __restrict__ Wl3,
                                                   const float* __restrict__ bl3,
                                                   const float* __restrict__ Wl,
                                                   const float* __restrict__ bl,
                                                   float* __restrict__ out) {
    __shared__ float gs[256];
    __shared__ float h2[128];
    __shared__ float h3[128];
    int g = blockIdx.x;
    int t = threadIdx.x;
    gs[t]       = g_pool[g * 256 + t];
    gs[t + 128] = g_pool[g * 256 + 128 + t];
    __syncthreads();
    float a = bl2[t];
    for (int k = 0; k < 256; k++) a += gs[k] * Wl2[k * 128 + t];
    h2[t] = fmaxf(a, 0.f);
    __syncthreads();
    float b = bl3[t];
    for (int k = 0; k < 128; k++) b += h2[k] * Wl3[k * 128 + t];
    h3[t] = fmaxf(b, 0.f);
    __syncthreads();
    if (t < 10) {
        float c = bl[t];
        for (int k = 0; k < 128; k++) c += h3[k] * Wl[k * 10 + t];
        out[g * 10 + t] = c;
    }
}

// ---------------- launch ---------------------------------------------------------

extern "C" void kernel_launch(void* const* d_in, const int* in_sizes, int n_in,
                              void* d_out, int out_size) {
    const float* x     = (const float*)d_in[0];
    const int*   ei    = (const int*)d_in[1];
    const int*   batch = (const int*)d_in[2];
    const float *W1 = (const float*)d_in[3],  *b1 = (const float*)d_in[4];
    const float *W2 = (const float*)d_in[5],  *b2 = (const float*)d_in[6];
    const float *W3 = (const float*)d_in[7],  *b3 = (const float*)d_in[8];
    const float *W4 = (const float*)d_in[9],  *b4 = (const float*)d_in[10];
    const float *Wl2 = (const float*)d_in[11], *bl2 = (const float*)d_in[12];
    const float *Wl3 = (const float*)d_in[13], *bl3 = (const float*)d_in[14];
    const float *Wl  = (const float*)d_in[15], *bl  = (const float*)d_in[16];
    float* out = (float*)d_out;

    const int* esrc = ei;
    const int* edst = ei + NE;

    cudaFuncSetAttribute(gemm_mma, cudaFuncAttributeMaxDynamicSharedMemorySize, GT_SMEM);

    // preprocessing + weight conversion (conv_w_all also zeroes g_cnt)
    conv_w_all<<<(163840 + 255) / 256, 256>>>(W2, W3, W4);
    count_kernel<<<(NE + 255) / 256, 256>>>(edst);
    scan1_kernel<<<SCAN_B, 256>>>();
    scan2_kernel<<<1, 256>>>();
    finalize_kernel<<<(NN + 255) / 256, 256>>>();
    fill_kernel<<<(NE + 255) / 256, 256>>>(esrc, edst);

    const int AGG_GRID = (NN + 7) / 8;
    dim3 ggrid(TM, 2);

    // layer 1: fused agg9 + GEMM(9->128) + relu -> g_h16 (stride 128)
    layer1_kernel<<<AGG_GRID, 256>>>(x, W1, b1);

    // layer 2: agg(F=128) -> fp16 A ; mma GEMM K=128 -> g_h16 (stride 256)
    agg_f16<128><<<AGG_GRID, 256>>>();
    gemm_mma<<<ggrid, 256, GT_SMEM>>>(b2, 1, 128, 0);

    // layer 3
    agg_f16<256><<<AGG_GRID, 256>>>();
    gemm_mma<<<ggrid, 256, GT_SMEM>>>(b3, 1, 256, 1);

    // layer 4 (no relu)
    agg_f16<256><<<AGG_GRID, 256>>>();
    gemm_mma<<<ggrid, 256, GT_SMEM>>>(b4, 0, 256, 2);

    // pool + head
    pool_kernel<<<(NN + 63) / 64, 256>>>(batch);
    head_kernel<<<NG, 128>>>(Wl2, bl2, Wl3, bl3, Wl, bl, out);
}

// round 14
// speedup vs baseline: 1.7201x; 1.0621x over previous
#include <cuda_runtime.h>
#include <cuda_fp16.h>
#include <math.h>

#define NN 50000
#define NE 800000
#define NG 64
#define SCAN_B ((NN + 255) / 256)
#define TM ((NN + 127) / 128)   // 391 m-tiles

typedef unsigned long long u64;
typedef unsigned int u32;

// ---------------- scratch (device globals; no allocation allowed) -------------
__device__ __half g_h16[(size_t)NN * 256];   // layer activations, fp16
__device__ __half g_A16[(size_t)NN * 256];   // aggregated activations (GEMM A), fp16
__device__ float g_dinv[NN];
__device__ int   g_cnt[NN];
__device__ int   g_off[NN + 1];
__device__ int   g_cur[NN];
__device__ int   g_bsum[SCAN_B];
__device__ int   g_csr_src[NE];
__device__ float g_csr_norm[NE];
__device__ float g_pool[NG * 256];
// fp16 weights per layer (0:W2 K=128, 1:W3, 2:W4)
__device__ unsigned short g_Wh[3][256 * 256];

// ---------------- PTX helpers ---------------------------------------------------

__device__ __forceinline__ u32 smem_u32(const void* p) {
    u32 a;
    asm("{ .reg .u64 t; cvta.to.shared.u64 t, %1; cvt.u32.u64 %0, t; }" : "=r"(a) : "l"(p));
    return a;
}
__device__ __forceinline__ void ldmx4(u32* r, u32 a) {
    asm volatile("ldmatrix.sync.aligned.m8n8.x4.shared.b16 {%0,%1,%2,%3}, [%4];"
                 : "=r"(r[0]), "=r"(r[1]), "=r"(r[2]), "=r"(r[3]) : "r"(a));
}
__device__ __forceinline__ void ldmx4t(u32* r, u32 a) {
    asm volatile("ldmatrix.sync.aligned.m8n8.x4.trans.shared.b16 {%0,%1,%2,%3}, [%4];"
                 : "=r"(r[0]), "=r"(r[1]), "=r"(r[2]), "=r"(r[3]) : "r"(a));
}
__device__ __forceinline__ void mma16816h(float* c, const u32* a, const u32* b) {
    asm volatile(
        "mma.sync.aligned.m16n8k16.row.col.f32.f16.f16.f32 "
        "{%0,%1,%2,%3}, {%4,%5,%6,%7}, {%8,%9}, {%0,%1,%2,%3};"
        : "+f"(c[0]), "+f"(c[1]), "+f"(c[2]), "+f"(c[3])
        : "r"(a[0]), "r"(a[1]), "r"(a[2]), "r"(a[3]), "r"(b[0]), "r"(b[1]));
}
__device__ __forceinline__ void cp16(u32 dst, const void* src, u32 sz) {
    asm volatile("cp.async.cg.shared.global [%0], [%1], 16, %2;"
                 :: "r"(dst), "l"(src), "r"(sz) : "memory");
}
__device__ __forceinline__ void cp_commit() {
    asm volatile("cp.async.commit_group;" ::: "memory");
}
template <int N>
__device__ __forceinline__ void cp_wait() {
    asm volatile("cp.async.wait_group %0;" :: "n"(N) : "memory");
}
__device__ __forceinline__ float h2f_bits(unsigned short bits) {
    __half h = __ushort_as_half(bits);   // bit reinterpretation, NOT value conversion
    return __half2float(h);
}

// ---------------- preprocessing ----------------------------------------------

__global__ void count_kernel(const int* __restrict__ dst) {
    int e = blockIdx.x * blockDim.x + threadIdx.x;
    if (e < NE) atomicAdd(&g_cnt[dst[e]], 1);
}

__global__ void scan1_kernel() {
    __shared__ int s[256];
    int tid = threadIdx.x;
    int idx = blockIdx.x * 256 + tid;
    int v = (idx < NN) ? g_cnt[idx] : 0;
    s[tid] = v;
    __syncthreads();
#pragma unroll
    for (int o = 1; o < 256; o <<= 1) {
        int t = (tid >= o) ? s[tid - o] : 0;
        __syncthreads();
        s[tid] += t;
        __syncthreads();
    }
    if (idx < NN) g_off[idx] = s[tid] - v;
    if (tid == 255) g_bsum[blockIdx.x] = s[255];
}

__global__ void scan2_kernel() {
    __shared__ int s[256];
    int tid = threadIdx.x;
    int v = (tid < SCAN_B) ? g_bsum[tid] : 0;
    s[tid] = v;
    __syncthreads();
#pragma unroll
    for (int o = 1; o < 256; o <<= 1) {
        int t = (tid >= o) ? s[tid - o] : 0;
        __syncthreads();
        s[tid] += t;
        __syncthreads();
    }
    if (tid < SCAN_B) g_bsum[tid] = s[tid] - v;
}

__global__ void finalize_kernel() {
    int v = blockIdx.x * blockDim.x + threadIdx.x;
    if (v < NN) {
        int off = g_off[v] + g_bsum[v >> 8];
        g_off[v] = off;
        g_cur[v] = off;
        g_dinv[v] = rsqrtf((float)g_cnt[v] + 1.0f);
    }
    if (v < NG * 256) g_pool[v] = -INFINITY;   // fused pool init
    if (v == 0) g_off[NN] = NE;
}

__global__ void fill_kernel(const int* __restrict__ src,
                            const int* __restrict__ dst) {
    int e = blockIdx.x * blockDim.x + threadIdx.x;
    if (e < NE) {
        int s = src[e];
        int d = dst[e];
        int pos = atomicAdd(&g_cur[d], 1);
        g_csr_src[pos] = s;
        g_csr_norm[pos] = g_dinv[s] * g_dinv[d];
    }
}

// ---------------- weight conversion (fp16) + zero counters ----------------------

__global__ void conv_w_all(const float* __restrict__ W2,
                           const float* __restrict__ W3,
                           const float* __restrict__ W4) {
    int i = blockIdx.x * 256 + threadIdx.x;
    if (i < NN) g_cnt[i] = 0;   // fused zero_cnt
    const float* W;
    unsigned short* dh;
    int off;
    if (i < 32768)       { W = W2; off = i;           dh = g_Wh[0]; }
    else if (i < 98304)  { W = W3; off = i - 32768;   dh = g_Wh[1]; }
    else if (i < 163840) { W = W4; off = i - 98304;   dh = g_Wh[2]; }
    else return;
    dh[off] = __half_as_ushort(__float2half_rn(W[off]));
}

// ---------------- fused layer 1: agg9 + [N,9]@[9,128] + bias + relu -> fp16 -----

__global__ __launch_bounds__(256) void layer1_kernel(const float* __restrict__ x,
                                                     const float* __restrict__ W1,
                                                     const float* __restrict__ b1) {
    __shared__ float Ws[9 * 128];
    __shared__ float Bs[128];
    int tid = threadIdx.x;
    for (int i = tid; i < 9 * 128; i += 256) Ws[i] = W1[i];
    if (tid < 128) Bs[tid] = b1[tid];
    __syncthreads();

    int warp = (blockIdx.x * 256 + tid) >> 5;
    int lane = tid & 31;
    if (warp >= NN) return;
    int v = warp;
    float dv = g_dinv[v];
    float acc = 0.f;
    if (lane < 9) acc = dv * dv * x[v * 9 + lane];
    int e0 = g_off[v], e1 = g_off[v + 1];
    for (int e = e0; e < e1; e++) {
        int s = g_csr_src[e];
        float nrm = g_csr_norm[e];
        if (lane < 9) acc += nrm * x[s * 9 + lane];
    }
    float ak[9];
#pragma unroll
    for (int k = 0; k < 9; k++) ak[k] = __shfl_sync(0xffffffffu, acc, k);

    int f = lane * 4;
    float o0 = Bs[f], o1 = Bs[f + 1], o2 = Bs[f + 2], o3 = Bs[f + 3];
#pragma unroll
    for (int k = 0; k < 9; k++) {
        float a = ak[k];
        const float* wr = &Ws[k * 128 + f];
        o0 += a * wr[0]; o1 += a * wr[1]; o2 += a * wr[2]; o3 += a * wr[3];
    }
    o0 = fmaxf(o0, 0.f); o1 = fmaxf(o1, 0.f);
    o2 = fmaxf(o2, 0.f); o3 = fmaxf(o3, 0.f);
    __half2* dst = (__half2*)(g_h16 + (size_t)v * 128 + f);
    dst[0] = __floats2half2_rn(o0, o1);
    dst[1] = __floats2half2_rn(o2, o3);
}

// ---------------- aggregation: gather fp16 rows -> fp16 A operand ---------------

template <int F>
__global__ __launch_bounds__(256) void agg_f16() {
    int warp = (blockIdx.x * blockDim.x + threadIdx.x) >> 5;
    int lane = threadIdx.x & 31;
    if (warp >= NN) return;
    const int v = warp;

    float acc[F / 32];
    float dv = g_dinv[v];
    float w = dv * dv;
    if (F == 256) {
        uint4 q = ((const uint4*)g_h16)[(size_t)v * 32 + lane];
        __half2* h = (__half2*)&q;
#pragma unroll
        for (int j = 0; j < 4; j++) {
            float2 f2 = __half22float2(h[j]);
            acc[2 * j] = w * f2.x; acc[2 * j + 1] = w * f2.y;
        }
    } else {
        uint2 q = ((const uint2*)g_h16)[(size_t)v * 32 + lane];
        __half2* h = (__half2*)&q;
#pragma unroll
        for (int j = 0; j < 2; j++) {
            float2 f2 = __half22float2(h[j]);
            acc[2 * j] = w * f2.x; acc[2 * j + 1] = w * f2.y;
        }
    }

    int e0 = g_off[v], e1 = g_off[v + 1];
    int e = e0;
    for (; e + 4 <= e1; e += 4) {
        int s0 = g_csr_src[e],     s1 = g_csr_src[e + 1];
        int s2 = g_csr_src[e + 2], s3 = g_csr_src[e + 3];
        float n0 = g_csr_norm[e],     n1 = g_csr_norm[e + 1];
        float n2 = g_csr_norm[e + 2], n3 = g_csr_norm[e + 3];
        if (F == 256) {
            uint4 q0 = ((const uint4*)g_h16)[(size_t)s0 * 32 + lane];
            uint4 q1 = ((const uint4*)g_h16)[(size_t)s1 * 32 + lane];
            uint4 q2 = ((const uint4*)g_h16)[(size_t)s2 * 32 + lane];
            uint4 q3 = ((const uint4*)g_h16)[(size_t)s3 * 32 + lane];
            __half2 *h0 = (__half2*)&q0, *h1 = (__half2*)&q1;
            __half2 *h2 = (__half2*)&q2, *h3 = (__half2*)&q3;
#pragma unroll
            for (int j = 0; j < 4; j++) {
                float2 f0 = __half22float2(h0[j]), f1 = __half22float2(h1[j]);
                float2 f2 = __half22float2(h2[j]), f3 = __half22float2(h3[j]);
                acc[2 * j]     += n0 * f0.x + n1 * f1.x + n2 * f2.x + n3 * f3.x;
                acc[2 * j + 1] += n0 * f0.y + n1 * f1.y + n2 * f2.y + n3 * f3.y;
            }
        } else {
            uint2 q0 = ((const uint2*)g_h16)[(size_t)s0 * 32 + lane];
            uint2 q1 = ((const uint2*)g_h16)[(size_t)s1 * 32 + lane];
            uint2 q2 = ((const uint2*)g_h16)[(size_t)s2 * 32 + lane];
            uint2 q3 = ((const uint2*)g_h16)[(size_t)s3 * 32 + lane];
            __half2 *h0 = (__half2*)&q0, *h1 = (__half2*)&q1;
            __half2 *h2 = (__half2*)&q2, *h3 = (__half2*)&q3;
#pragma unroll
            for (int j = 0; j < 2; j++) {
                float2 f0 = __half22float2(h0[j]), f1 = __half22float2(h1[j]);
                float2 f2 = __half22float2(h2[j]), f3 = __half22float2(h3[j]);
                acc[2 * j]     += n0 * f0.x + n1 * f1.x + n2 * f2.x + n3 * f3.x;
                acc[2 * j + 1] += n0 * f0.y + n1 * f1.y + n2 * f2.y + n3 * f3.y;
            }
        }
    }
    for (; e < e1; e++) {
        int s = g_csr_src[e];
        float nrm = g_csr_norm[e];
        if (F == 256) {
            uint4 q0 = ((const uint4*)g_h16)[(size_t)s * 32 + lane];
            __half2* h0 = (__half2*)&q0;
#pragma unroll
            for (int j = 0; j < 4; j++) {
                float2 f2 = __half22float2(h0[j]);
                acc[2 * j] += nrm * f2.x; acc[2 * j + 1] += nrm * f2.y;
            }
        } else {
            uint2 q0 = ((const uint2*)g_h16)[(size_t)s * 32 + lane];
            __half2* h0 = (__half2*)&q0;
#pragma unroll
            for (int j = 0; j < 2; j++) {
                float2 f2 = __half22float2(h0[j]);
                acc[2 * j] += nrm * f2.x; acc[2 * j + 1] += nrm * f2.y;
            }
        }
    }

    if (F == 256) {
        uint4 o;
        __half2* ho = (__half2*)&o;
#pragma unroll
        for (int j = 0; j < 4; j++) ho[j] = __floats2half2_rn(acc[2 * j], acc[2 * j + 1]);
        ((uint4*)g_A16)[(size_t)v * 32 + lane] = o;
    } else {
        uint2 o;
        __half2* ho = (__half2*)&o;
#pragma unroll
        for (int j = 0; j < 2; j++) ho[j] = __floats2half2_rn(acc[2 * j], acc[2 * j + 1]);
        ((uint2*)g_A16)[(size_t)v * 32 + lane] = o;
    }
}

// ---------------- global max pool helper -----------------------------------------

__device__ __forceinline__ void atomicMaxF(float* a, float v) {
    if (v >= 0.f) atomicMax((int*)a, __float_as_int(v));
    else          atomicMin((unsigned int*)a, __float_as_uint(v));
}

// ---------------- mma.sync fp16 GEMM (single-pass W), cp.async double-buffered --
// BM=128, BN=128, BK=32; 8 warps (4x2), warp tile 32x64
// POOL=false: output fp16 -> g_h16.  POOL=true: segmented max -> g_pool (no store)

#define SA 40
#define SB 136
#define A_ST (128 * SA)
#define B_ST (32 * SB)
#define SO 132   // pooled out tile stride (shorts)
#define GT_SMEM ((2 * A_ST + 2 * B_ST) * 2)   // 37888 B >= 128*SO*2 = 33792

template <bool POOL>
__global__ __launch_bounds__(256) void gemm_mma(const float* __restrict__ bias,
                                                int relu, int K, int wl,
                                                const int* __restrict__ batch) {
    extern __shared__ unsigned short smem[];
    unsigned short* Aa = smem;                  // [2][A_ST]
    unsigned short* Bh = Aa + 2 * A_ST;         // [2][B_ST]
    __shared__ float bs[128];
    __shared__ int sbatch[128];

    const unsigned short* GWh = g_Wh[wl];

    int tid = threadIdx.x, lane = tid & 31, wid = tid >> 5;
    int tm = blockIdx.x, tn = blockIdx.y;
    int wm = wid & 3, wn = wid >> 2;
    if (tid < 128) {
        bs[tid] = bias[tn * 128 + tid];
        if (POOL) {
            int v = tm * 128 + tid;
            sbatch[tid] = (v < NN) ? batch[v] : -1;
        }
    }

    float c[16][4];
#pragma unroll
    for (int i = 0; i < 16; i++)
#pragma unroll
        for (int j = 0; j < 4; j++) c[i][j] = 0.f;

    u32 sAa = smem_u32(Aa);
    u32 sBh = smem_u32(Bh);

    auto issue = [&](int st, int k0) {
#pragma unroll
        for (int i = 0; i < 2; i++) {
            int idx = tid + i * 256;
            int row = idx >> 2, cg = idx & 3;
            int grow = tm * 128 + row;
            u32 sz = (grow < NN) ? 16u : 0u;
            size_t gof = (size_t)grow * K + k0 + cg * 8;
            u32 dof = (u32)((st * A_ST + row * SA + cg * 8) * 2);
            cp16(sAa + dof, g_A16 + gof, sz);
        }
#pragma unroll
        for (int i = 0; i < 2; i++) {
            int idx = tid + i * 256;
            int row = idx >> 4, cg = idx & 15;
            size_t gof = (size_t)(k0 + row) * 256 + tn * 128 + cg * 8;
            u32 dof = (u32)((st * B_ST + row * SB + cg * 8) * 2);
            cp16(sBh + dof, GWh + gof, 16u);
        }
        cp_commit();
    };

    const int niter = K >> 5;
    issue(0, 0);
    for (int it = 0; it < niter; it++) {
        int cur = it & 1;
        if (it + 1 < niter) {
            issue((it + 1) & 1, (it + 1) << 5);
            cp_wait<1>();
        } else {
            cp_wait<0>();
        }
        __syncthreads();

        u32 aof = (u32)(cur * A_ST * 2), bof = (u32)(cur * B_ST * 2);
#pragma unroll
        for (int ks = 0; ks < 2; ks++) {
            u32 ah[2][4], bh[4][4];
            int ar = wm * 32 + (lane & 15);
            int ac = ks * 16 + (lane >> 4) * 8;
            ldmx4(ah[0], sAa + aof + (u32)((ar * SA + ac) * 2));
            ldmx4(ah[1], sAa + aof + (u32)(((ar + 16) * SA + ac) * 2));
            int br = ks * 16 + (lane & 15);
#pragma unroll
            for (int g = 0; g < 4; g++) {
                int bc = wn * 64 + g * 16 + (lane >> 4) * 8;
                ldmx4t(bh[g], sBh + bof + (u32)((br * SB + bc) * 2));
            }
#pragma unroll
            for (int mt = 0; mt < 2; mt++)
#pragma unroll
                for (int nt = 0; nt < 8; nt++) {
                    mma16816h(c[mt * 8 + nt], ah[mt], &bh[nt >> 1][(nt & 1) * 2]);
                }
        }
        __syncthreads();
    }

    if (!POOL) {
        // epilogue: bias + optional relu -> fp16 g_h16 [NN][256]
#pragma unroll
        for (int mt = 0; mt < 2; mt++) {
#pragma unroll
            for (int nt = 0; nt < 8; nt++) {
                int r0 = tm * 128 + wm * 32 + mt * 16 + (lane >> 2);
                int cl = wn * 64 + nt * 8 + (lane & 3) * 2;
                int col = tn * 128 + cl;
                float b0 = bs[cl], b1 = bs[cl + 1];
                float v0 = c[mt * 8 + nt][0] + b0;
                float v1 = c[mt * 8 + nt][1] + b1;
                float v2 = c[mt * 8 + nt][2] + b0;
                float v3 = c[mt * 8 + nt][3] + b1;
                if (relu) {
                    v0 = fmaxf(v0, 0.f); v1 = fmaxf(v1, 0.f);
                    v2 = fmaxf(v2, 0.f); v3 = fmaxf(v3, 0.f);
                }
                if (r0 < NN)
                    *(__half2*)(g_h16 + (size_t)r0 * 256 + col) = __floats2half2_rn(v0, v1);
                if (r0 + 8 < NN)
                    *(__half2*)(g_h16 + (size_t)(r0 + 8) * 256 + col) = __floats2half2_rn(v2, v3);
            }
        }
    } else {
        // epilogue: stage fp16 tile in (reused) smem, segmented max -> g_pool
        unsigned short* ot = smem;   // [128][SO]
#pragma unroll
        for (int mt = 0; mt < 2; mt++) {
#pragma unroll
            for (int nt = 0; nt < 8; nt++) {
                int lr = wm * 32 + mt * 16 + (lane >> 2);
                int cl = wn * 64 + nt * 8 + (lane & 3) * 2;
                float b0 = bs[cl], b1 = bs[cl + 1];
                *(__half2*)(ot + lr * SO + cl) =
                    __floats2half2_rn(c[mt * 8 + nt][0] + b0, c[mt * 8 + nt][1] + b1);
                *(__half2*)(ot + (lr + 8) * SO + cl) =
                    __floats2half2_rn(c[mt * 8 + nt][2] + b0, c[mt * 8 + nt][3] + b1);
            }
        }
        __syncthreads();

        int colp = tid & 127;
        int half = tid >> 7;
        int base = half * 64;
        if (tm * 128 + base < NN) {
            float m = -INFINITY;
            int cg = sbatch[base];
            for (int r = 0; r < 64; r++) {
                int lr = base + r;
                if (tm * 128 + lr >= NN) break;
                int g = sbatch[lr];
                if (g != cg) {
                    atomicMaxF(&g_pool[cg * 256 + tn * 128 + colp], m);
                    m = -INFINITY;
                    cg = g;
                }
                m = fmaxf(m, h2f_bits(ot[lr * SO + colp]));   // bit-reinterpret fp16
            }
            atomicMaxF(&g_pool[cg * 256 + tn * 128 + colp], m);
        }
    }
}

// ---------------- dense head ----------------------------------------------------

__global__ __launch_bounds__(128) void head_kernel(const float* __restrict__ Wl2,
                                                   const float* __restrict__ bl2,
                                                   const float* __restrict__ Wl3,
                                                   const float* __restrict__ bl3,
                                                   const float* __restrict__ Wl,
                                                   const float* __restrict__ bl,
                                                   float* __restrict__ out) {
    __shared__ float gs[256];
    __shared__ float h2[128];
    __shared__ float h3[128];
    int g = blockIdx.x;
    int t = threadIdx.x;
    gs[t]       = g_pool[g * 256 + t];
    gs[t + 128] = g_pool[g * 256 + 128 + t];
    __syncthreads();
    float a = bl2[t];
    for (int k = 0; k < 256; k++) a += gs[k] * Wl2[k * 128 + t];
    h2[t] = fmaxf(a, 0.f);
    __syncthreads();
    float b = bl3[t];
    for (int k = 0; k < 128; k++) b += h2[k] * Wl3[k * 128 + t];
    h3[t] = fmaxf(b, 0.f);
    __syncthreads();
    if (t < 10) {
        float c = bl[t];
        for (int k = 0; k < 128; k++) c += h3[k] * Wl[k * 10 + t];
        out[g * 10 + t] = c;
    }
}

// ---------------- launch ---------------------------------------------------------

extern "C" void kernel_launch(void* const* d_in, const int* in_sizes, int n_in,
                              void* d_out, int out_size) {
    const float* x     = (const float*)d_in[0];
    const int*   ei    = (const int*)d_in[1];
    const int*   batch = (const int*)d_in[2];
    const float *W1 = (const float*)d_in[3],  *b1 = (const float*)d_in[4];
    const float *W2 = (const float*)d_in[5],  *b2 = (const float*)d_in[6];
    const float *W3 = (const float*)d_in[7],  *b3 = (const float*)d_in[8];
    const float *W4 = (const float*)d_in[9],  *b4 = (const float*)d_in[10];
    const float *Wl2 = (const float*)d_in[11], *bl2 = (const float*)d_in[12];
    const float *Wl3 = (const float*)d_in[13], *bl3 = (const float*)d_in[14];
    const float *Wl  = (const float*)d_in[15], *bl  = (const float*)d_in[16];
    float* out = (float*)d_out;

    const int* esrc = ei;
    const int* edst = ei + NE;

    cudaFuncSetAttribute(gemm_mma<false>, cudaFuncAttributeMaxDynamicSharedMemorySize, GT_SMEM);
    cudaFuncSetAttribute(gemm_mma<true>,  cudaFuncAttributeMaxDynamicSharedMemorySize, GT_SMEM);

    // preprocessing + weight conversion (conv_w_all also zeroes g_cnt)
    conv_w_all<<<(163840 + 255) / 256, 256>>>(W2, W3, W4);
    count_kernel<<<(NE + 255) / 256, 256>>>(edst);
    scan1_kernel<<<SCAN_B, 256>>>();
    scan2_kernel<<<1, 256>>>();
    finalize_kernel<<<(NN + 255) / 256, 256>>>();
    fill_kernel<<<(NE + 255) / 256, 256>>>(esrc, edst);

    const int AGG_GRID = (NN + 7) / 8;
    dim3 ggrid(TM, 2);

    // layer 1: fused agg9 + GEMM(9->128) + relu -> g_h16 (stride 128)
    layer1_kernel<<<AGG_GRID, 256>>>(x, W1, b1);

    // layer 2: agg(F=128) -> fp16 A ; mma GEMM K=128 -> g_h16 (stride 256)
    agg_f16<128><<<AGG_GRID, 256>>>();
    gemm_mma<false><<<ggrid, 256, GT_SMEM>>>(b2, 1, 128, 0, batch);

    // layer 3
    agg_f16<256><<<AGG_GRID, 256>>>();
    gemm_mma<false><<<ggrid, 256, GT_SMEM>>>(b3, 1, 256, 1, batch);

    // layer 4: GEMM + fused segmented max-pool -> g_pool (no activation store)
    agg_f16<256><<<AGG_GRID, 256>>>();
    gemm_mma<true><<<ggrid, 256, GT_SMEM>>>(b4, 0, 256, 2, batch);

    // head
    head_kernel<<<NG, 128>>>(Wl2, bl2, Wl3, bl3, Wl, bl, out);
}

// round 15
// speedup vs baseline: 1.7713x; 1.0298x over previous
#include <cuda_runtime.h>
#include <cuda_fp16.h>
#include <math.h>

#define NN 50000
#define NE 800000
#define NG 64
#define SCAN_B ((NN + 255) / 256)
#define TM ((NN + 127) / 128)   // 391 m-tiles

typedef unsigned long long u64;
typedef unsigned int u32;

// ---------------- scratch (device globals; no allocation allowed) -------------
__device__ __half g_h16[(size_t)NN * 256];   // layer activations, fp16
__device__ __half g_A16[(size_t)NN * 256];   // aggregated activations (GEMM A), fp16
__device__ float g_dinv[NN];
__device__ int   g_cnt[NN];
__device__ int   g_off[NN + 1];
__device__ int   g_cur[NN];
__device__ int   g_bsum[SCAN_B];
__device__ int   g_csr_src[NE];
__device__ float g_csr_norm[NE];
__device__ float g_pool[NG * 256];
// fp16 weights per layer (0:W2 K=128, 1:W3, 2:W4)
__device__ unsigned short g_Wh[3][256 * 256];

// ---------------- PTX helpers ---------------------------------------------------

__device__ __forceinline__ u32 smem_u32(const void* p) {
    u32 a;
    asm("{ .reg .u64 t; cvta.to.shared.u64 t, %1; cvt.u32.u64 %0, t; }" : "=r"(a) : "l"(p));
    return a;
}
__device__ __forceinline__ void ldmx4(u32* r, u32 a) {
    asm volatile("ldmatrix.sync.aligned.m8n8.x4.shared.b16 {%0,%1,%2,%3}, [%4];"
                 : "=r"(r[0]), "=r"(r[1]), "=r"(r[2]), "=r"(r[3]) : "r"(a));
}
__device__ __forceinline__ void ldmx4t(u32* r, u32 a) {
    asm volatile("ldmatrix.sync.aligned.m8n8.x4.trans.shared.b16 {%0,%1,%2,%3}, [%4];"
                 : "=r"(r[0]), "=r"(r[1]), "=r"(r[2]), "=r"(r[3]) : "r"(a));
}
__device__ __forceinline__ void mma16816h(float* c, const u32* a, const u32* b) {
    asm volatile(
        "mma.sync.aligned.m16n8k16.row.col.f32.f16.f16.f32 "
        "{%0,%1,%2,%3}, {%4,%5,%6,%7}, {%8,%9}, {%0,%1,%2,%3};"
        : "+f"(c[0]), "+f"(c[1]), "+f"(c[2]), "+f"(c[3])
        : "r"(a[0]), "r"(a[1]), "r"(a[2]), "r"(a[3]), "r"(b[0]), "r"(b[1]));
}
__device__ __forceinline__ void cp16(u32 dst, const void* src, u32 sz) {
    asm volatile("cp.async.cg.shared.global [%0], [%1], 16, %2;"
                 :: "r"(dst), "l"(src), "r"(sz) : "memory");
}
__device__ __forceinline__ void cp_commit() {
    asm volatile("cp.async.commit_group;" ::: "memory");
}
template <int N>
__device__ __forceinline__ void cp_wait() {
    asm volatile("cp.async.wait_group %0;" :: "n"(N) : "memory");
}
__device__ __forceinline__ float h2f_bits(unsigned short bits) {
    __half h = __ushort_as_half(bits);
    return __half2float(h);
}

// ---------------- preprocessing ----------------------------------------------

__global__ void count_kernel(const int* __restrict__ dst) {
    int e = blockIdx.x * blockDim.x + threadIdx.x;
    if (e < NE) atomicAdd(&g_cnt[dst[e]], 1);
}

__global__ void scan1_kernel() {
    __shared__ int s[256];
    int tid = threadIdx.x;
    int idx = blockIdx.x * 256 + tid;
    int v = (idx < NN) ? g_cnt[idx] : 0;
    s[tid] = v;
    __syncthreads();
#pragma unroll
    for (int o = 1; o < 256; o <<= 1) {
        int t = (tid >= o) ? s[tid - o] : 0;
        __syncthreads();
        s[tid] += t;
        __syncthreads();
    }
    if (idx < NN) g_off[idx] = s[tid] - v;
    if (tid == 255) g_bsum[blockIdx.x] = s[255];
}

// finalize with inline block-base reduction (replaces scan2)
__global__ void finalize_kernel() {
    __shared__ int s[256];
    int tid = threadIdx.x;
    int b = blockIdx.x;
    // base = sum of g_bsum[0..b-1]
    int part = (tid < SCAN_B && tid < b) ? g_bsum[tid] : 0;
    s[tid] = part;
    __syncthreads();
#pragma unroll
    for (int o = 128; o > 0; o >>= 1) {
        if (tid < o) s[tid] += s[tid + o];
        __syncthreads();
    }
    int base = s[0];

    int v = b * 256 + tid;
    if (v < NN) {
        int off = g_off[v] + base;
        g_off[v] = off;
        g_cur[v] = off;
        g_dinv[v] = rsqrtf((float)g_cnt[v] + 1.0f);
    }
    if (v < NG * 256) g_pool[v] = -INFINITY;   // fused pool init
    if (v == 0) g_off[NN] = NE;
}

__global__ void fill_kernel(const int* __restrict__ src,
                            const int* __restrict__ dst) {
    int e = blockIdx.x * blockDim.x + threadIdx.x;
    if (e < NE) {
        int s = src[e];
        int d = dst[e];
        int pos = atomicAdd(&g_cur[d], 1);
        g_csr_src[pos] = s;
        g_csr_norm[pos] = g_dinv[s] * g_dinv[d];
    }
}

// ---------------- weight conversion (fp16) + zero counters ----------------------

__global__ void conv_w_all(const float* __restrict__ W2,
                           const float* __restrict__ W3,
                           const float* __restrict__ W4) {
    int i = blockIdx.x * 256 + threadIdx.x;
    if (i < NN) g_cnt[i] = 0;   // fused zero_cnt
    const float* W;
    unsigned short* dh;
    int off;
    if (i < 32768)       { W = W2; off = i;           dh = g_Wh[0]; }
    else if (i < 98304)  { W = W3; off = i - 32768;   dh = g_Wh[1]; }
    else if (i < 163840) { W = W4; off = i - 98304;   dh = g_Wh[2]; }
    else return;
    dh[off] = __half_as_ushort(__float2half_rn(W[off]));
}

// ---------------- fused layer 1: agg9 + [N,9]@[9,128] + bias + relu -> fp16 -----

__global__ __launch_bounds__(256) void layer1_kernel(const float* __restrict__ x,
                                                     const float* __restrict__ W1,
                                                     const float* __restrict__ b1) {
    __shared__ float Ws[9 * 128];
    __shared__ float Bs[128];
    int tid = threadIdx.x;
    for (int i = tid; i < 9 * 128; i += 256) Ws[i] = W1[i];
    if (tid < 128) Bs[tid] = b1[tid];
    __syncthreads();

    int warp = (blockIdx.x * 256 + tid) >> 5;
    int lane = tid & 31;
    if (warp >= NN) return;
    int v = warp;
    float dv = g_dinv[v];
    float acc = 0.f;
    if (lane < 9) acc = dv * dv * x[v * 9 + lane];
    int e0 = g_off[v], e1 = g_off[v + 1];
    for (int e = e0; e < e1; e++) {
        int s = g_csr_src[e];
        float nrm = g_csr_norm[e];
        if (lane < 9) acc += nrm * x[s * 9 + lane];
    }
    float ak[9];
#pragma unroll
    for (int k = 0; k < 9; k++) ak[k] = __shfl_sync(0xffffffffu, acc, k);

    int f = lane * 4;
    float o0 = Bs[f], o1 = Bs[f + 1], o2 = Bs[f + 2], o3 = Bs[f + 3];
#pragma unroll
    for (int k = 0; k < 9; k++) {
        float a = ak[k];
        const float* wr = &Ws[k * 128 + f];
        o0 += a * wr[0]; o1 += a * wr[1]; o2 += a * wr[2]; o3 += a * wr[3];
    }
    o0 = fmaxf(o0, 0.f); o1 = fmaxf(o1, 0.f);
    o2 = fmaxf(o2, 0.f); o3 = fmaxf(o3, 0.f);
    __half2* dst = (__half2*)(g_h16 + (size_t)v * 128 + f);
    dst[0] = __floats2half2_rn(o0, o1);
    dst[1] = __floats2half2_rn(o2, o3);
}

// ---------------- aggregation: gather fp16 rows -> fp16 A operand (x8 unroll) ---

template <int F>
__global__ __launch_bounds__(256) void agg_f16() {
    int warp = (blockIdx.x * blockDim.x + threadIdx.x) >> 5;
    int lane = threadIdx.x & 31;
    if (warp >= NN) return;
    const int v = warp;

    float acc[F / 32];
    float dv = g_dinv[v];
    float w = dv * dv;
    if (F == 256) {
        uint4 q = ((const uint4*)g_h16)[(size_t)v * 32 + lane];
        __half2* h = (__half2*)&q;
#pragma unroll
        for (int j = 0; j < 4; j++) {
            float2 f2 = __half22float2(h[j]);
            acc[2 * j] = w * f2.x; acc[2 * j + 1] = w * f2.y;
        }
    } else {
        uint2 q = ((const uint2*)g_h16)[(size_t)v * 32 + lane];
        __half2* h = (__half2*)&q;
#pragma unroll
        for (int j = 0; j < 2; j++) {
            float2 f2 = __half22float2(h[j]);
            acc[2 * j] = w * f2.x; acc[2 * j + 1] = w * f2.y;
        }
    }

    int e0 = g_off[v], e1 = g_off[v + 1];
    int e = e0;
    for (; e + 8 <= e1; e += 8) {
        int si[8];
        float ni[8];
#pragma unroll
        for (int u = 0; u < 8; u++) { si[u] = g_csr_src[e + u]; ni[u] = g_csr_norm[e + u]; }
        if (F == 256) {
            uint4 q[8];
#pragma unroll
            for (int u = 0; u < 8; u++) q[u] = ((const uint4*)g_h16)[(size_t)si[u] * 32 + lane];
#pragma unroll
            for (int u = 0; u < 8; u++) {
                __half2* h = (__half2*)&q[u];
                float n = ni[u];
#pragma unroll
                for (int j = 0; j < 4; j++) {
                    float2 f2 = __half22float2(h[j]);
                    acc[2 * j] += n * f2.x; acc[2 * j + 1] += n * f2.y;
                }
            }
        } else {
            uint2 q[8];
#pragma unroll
            for (int u = 0; u < 8; u++) q[u] = ((const uint2*)g_h16)[(size_t)si[u] * 32 + lane];
#pragma unroll
            for (int u = 0; u < 8; u++) {
                __half2* h = (__half2*)&q[u];
                float n = ni[u];
#pragma unroll
                for (int j = 0; j < 2; j++) {
                    float2 f2 = __half22float2(h[j]);
                    acc[2 * j] += n * f2.x; acc[2 * j + 1] += n * f2.y;
                }
            }
        }
    }
    for (; e < e1; e++) {
        int s = g_csr_src[e];
        float nrm = g_csr_norm[e];
        if (F == 256) {
            uint4 q0 = ((const uint4*)g_h16)[(size_t)s * 32 + lane];
            __half2* h0 = (__half2*)&q0;
#pragma unroll
            for (int j = 0; j < 4; j++) {
                float2 f2 = __half22float2(h0[j]);
                acc[2 * j] += nrm * f2.x; acc[2 * j + 1] += nrm * f2.y;
            }
        } else {
            uint2 q0 = ((const uint2*)g_h16)[(size_t)s * 32 + lane];
            __half2* h0 = (__half2*)&q0;
#pragma unroll
            for (int j = 0; j < 2; j++) {
                float2 f2 = __half22float2(h0[j]);
                acc[2 * j] += nrm * f2.x; acc[2 * j + 1] += nrm * f2.y;
            }
        }
    }

    if (F == 256) {
        uint4 o;
        __half2* ho = (__half2*)&o;
#pragma unroll
        for (int j = 0; j < 4; j++) ho[j] = __floats2half2_rn(acc[2 * j], acc[2 * j + 1]);
        ((uint4*)g_A16)[(size_t)v * 32 + lane] = o;
    } else {
        uint2 o;
        __half2* ho = (__half2*)&o;
#pragma unroll
        for (int j = 0; j < 2; j++) ho[j] = __floats2half2_rn(acc[2 * j], acc[2 * j + 1]);
        ((uint2*)g_A16)[(size_t)v * 32 + lane] = o;
    }
}

// ---------------- global max pool helper -----------------------------------------

__device__ __forceinline__ void atomicMaxF(float* a, float v) {
    if (v >= 0.f) atomicMax((int*)a, __float_as_int(v));
    else          atomicMin((unsigned int*)a, __float_as_uint(v));
}

// ---------------- mma.sync fp16 GEMM (single-pass W), cp.async double-buffered --
// BM=128, BN=128, BK=32; 8 warps (4x2), warp tile 32x64
// POOL=false: output fp16 -> g_h16.  POOL=true: segmented max -> g_pool (no store)

#define SA 40
#define SB 136
#define A_ST (128 * SA)
#define B_ST (32 * SB)
#define SO 132   // pooled out tile stride (shorts)
#define GT_SMEM ((2 * A_ST + 2 * B_ST) * 2)   // 37888 B >= 128*SO*2 = 33792

template <bool POOL>
__global__ __launch_bounds__(256) void gemm_mma(const float* __restrict__ bias,
                                                int relu, int K, int wl,
                                                const int* __restrict__ batch) {
    extern __shared__ unsigned short smem[];
    unsigned short* Aa = smem;                  // [2][A_ST]
    unsigned short* Bh = Aa + 2 * A_ST;         // [2][B_ST]
    __shared__ float bs[128];
    __shared__ int sbatch[128];

    const unsigned short* GWh = g_Wh[wl];

    int tid = threadIdx.x, lane = tid & 31, wid = tid >> 5;
    int tm = blockIdx.x, tn = blockIdx.y;
    int wm = wid & 3, wn = wid >> 2;
    if (tid < 128) {
        bs[tid] = bias[tn * 128 + tid];
        if (POOL) {
            int v = tm * 128 + tid;
            sbatch[tid] = (v < NN) ? batch[v] : -1;
        }
    }

    float c[16][4];
#pragma unroll
    for (int i = 0; i < 16; i++)
#pragma unroll
        for (int j = 0; j < 4; j++) c[i][j] = 0.f;

    u32 sAa = smem_u32(Aa);
    u32 sBh = smem_u32(Bh);

    auto issue = [&](int st, int k0) {
#pragma unroll
        for (int i = 0; i < 2; i++) {
            int idx = tid + i * 256;
            int row = idx >> 2, cg = idx & 3;
            int grow = tm * 128 + row;
            u32 sz = (grow < NN) ? 16u : 0u;
            size_t gof = (size_t)grow * K + k0 + cg * 8;
            u32 dof = (u32)((st * A_ST + row * SA + cg * 8) * 2);
            cp16(sAa + dof, g_A16 + gof, sz);
        }
#pragma unroll
        for (int i = 0; i < 2; i++) {
            int idx = tid + i * 256;
            int row = idx >> 4, cg = idx & 15;
            size_t gof = (size_t)(k0 + row) * 256 + tn * 128 + cg * 8;
            u32 dof = (u32)((st * B_ST + row * SB + cg * 8) * 2);
            cp16(sBh + dof, GWh + gof, 16u);
        }
        cp_commit();
    };

    const int niter = K >> 5;
    issue(0, 0);
    for (int it = 0; it < niter; it++) {
        int cur = it & 1;
        if (it + 1 < niter) {
            issue((it + 1) & 1, (it + 1) << 5);
            cp_wait<1>();
        } else {
            cp_wait<0>();
        }
        __syncthreads();

        u32 aof = (u32)(cur * A_ST * 2), bof = (u32)(cur * B_ST * 2);
#pragma unroll
        for (int ks = 0; ks < 2; ks++) {
            u32 ah[2][4], bh[4][4];
            int ar = wm * 32 + (lane & 15);
            int ac = ks * 16 + (lane >> 4) * 8;
            ldmx4(ah[0], sAa + aof + (u32)((ar * SA + ac) * 2));
            ldmx4(ah[1], sAa + aof + (u32)(((ar + 16) * SA + ac) * 2));
            int br = ks * 16 + (lane & 15);
#pragma unroll
            for (int g = 0; g < 4; g++) {
                int bc = wn * 64 + g * 16 + (lane >> 4) * 8;
                ldmx4t(bh[g], sBh + bof + (u32)((br * SB + bc) * 2));
            }
#pragma unroll
            for (int mt = 0; mt < 2; mt++)
#pragma unroll
                for (int nt = 0; nt < 8; nt++) {
                    mma16816h(c[mt * 8 + nt], ah[mt], &bh[nt >> 1][(nt & 1) * 2]);
                }
        }
        __syncthreads();
    }

    if (!POOL) {
#pragma unroll
        for (int mt = 0; mt < 2; mt++) {
#pragma unroll
            for (int nt = 0; nt < 8; nt++) {
                int r0 = tm * 128 + wm * 32 + mt * 16 + (lane >> 2);
                int cl = wn * 64 + nt * 8 + (lane & 3) * 2;
                int col = tn * 128 + cl;
                float b0 = bs[cl], b1 = bs[cl + 1];
                float v0 = c[mt * 8 + nt][0] + b0;
                float v1 = c[mt * 8 + nt][1] + b1;
                float v2 = c[mt * 8 + nt][2] + b0;
                float v3 = c[mt * 8 + nt][3] + b1;
                if (relu) {
                    v0 = fmaxf(v0, 0.f); v1 = fmaxf(v1, 0.f);
                    v2 = fmaxf(v2, 0.f); v3 = fmaxf(v3, 0.f);
                }
                if (r0 < NN)
                    *(__half2*)(g_h16 + (size_t)r0 * 256 + col) = __floats2half2_rn(v0, v1);
                if (r0 + 8 < NN)
                    *(__half2*)(g_h16 + (size_t)(r0 + 8) * 256 + col) = __floats2half2_rn(v2, v3);
            }
        }
    } else {
        unsigned short* ot = smem;   // [128][SO]
#pragma unroll
        for (int mt = 0; mt < 2; mt++) {
#pragma unroll
            for (int nt = 0; nt < 8; nt++) {
                int lr = wm * 32 + mt * 16 + (lane >> 2);
                int cl = wn * 64 + nt * 8 + (lane & 3) * 2;
                float b0 = bs[cl], b1 = bs[cl + 1];
                *(__half2*)(ot + lr * SO + cl) =
                    __floats2half2_rn(c[mt * 8 + nt][0] + b0, c[mt * 8 + nt][1] + b1);
                *(__half2*)(ot + (lr + 8) * SO + cl) =
                    __floats2half2_rn(c[mt * 8 + nt][2] + b0, c[mt * 8 + nt][3] + b1);
            }
        }
        __syncthreads();

        int colp = tid & 127;
        int half = tid >> 7;
        int base = half * 64;
        if (tm * 128 + base < NN) {
            float m = -INFINITY;
            int cg = sbatch[base];
            for (int r = 0; r < 64; r++) {
                int lr = base + r;
                if (tm * 128 + lr >= NN) break;
                int g = sbatch[lr];
                if (g != cg) {
                    atomicMaxF(&g_pool[cg * 256 + tn * 128 + colp], m);
                    m = -INFINITY;
                    cg = g;
                }
                m = fmaxf(m, h2f_bits(ot[lr * SO + colp]));
            }
            atomicMaxF(&g_pool[cg * 256 + tn * 128 + colp], m);
        }
    }
}

// ---------------- dense head ----------------------------------------------------

__global__ __launch_bounds__(128) void head_kernel(const float* __restrict__ Wl2,
                                                   const float* __restrict__ bl2,
                                                   const float* __restrict__ Wl3,
                                                   const float* __restrict__ bl3,
                                                   const float* __restrict__ Wl,
                                                   const float* __restrict__ bl,
                                                   float* __restrict__ out) {
    __shared__ float gs[256];
    __shared__ float h2[128];
    __shared__ float h3[128];
    int g = blockIdx.x;
    int t = threadIdx.x;
    gs[t]       = g_pool[g * 256 + t];
    gs[t + 128] = g_pool[g * 256 + 128 + t];
    __syncthreads();
    float a = bl2[t];
    for (int k = 0; k < 256; k++) a += gs[k] * Wl2[k * 128 + t];
    h2[t] = fmaxf(a, 0.f);
    __syncthreads();
    float b = bl3[t];
    for (int k = 0; k < 128; k++) b += h2[k] * Wl3[k * 128 + t];
    h3[t] = fmaxf(b, 0.f);
    __syncthreads();
    if (t < 10) {
        float c = bl[t];
        for (int k = 0; k < 128; k++) c += h3[k] * Wl[k * 10 + t];
        out[g * 10 + t] = c;
    }
}

// ---------------- launch ---------------------------------------------------------

extern "C" void kernel_launch(void* const* d_in, const int* in_sizes, int n_in,
                              void* d_out, int out_size) {
    const float* x     = (const float*)d_in[0];
    const int*   ei    = (const int*)d_in[1];
    const int*   batch = (const int*)d_in[2];
    const float *W1 = (const float*)d_in[3],  *b1 = (const float*)d_in[4];
    const float *W2 = (const float*)d_in[5],  *b2 = (const float*)d_in[6];
    const float *W3 = (const float*)d_in[7],  *b3 = (const float*)d_in[8];
    const float *W4 = (const float*)d_in[9],  *b4 = (const float*)d_in[10];
    const float *Wl2 = (const float*)d_in[11], *bl2 = (const float*)d_in[12];
    const float *Wl3 = (const float*)d_in[13], *bl3 = (const float*)d_in[14];
    const float *Wl  = (const float*)d_in[15], *bl  = (const float*)d_in[16];
    float* out = (float*)d_out;

    const int* esrc = ei;
    const int* edst = ei + NE;

    cudaFuncSetAttribute(gemm_mma<false>, cudaFuncAttributeMaxDynamicSharedMemorySize, GT_SMEM);
    cudaFuncSetAttribute(gemm_mma<true>,  cudaFuncAttributeMaxDynamicSharedMemorySize, GT_SMEM);

    // preprocessing + weight conversion (conv_w_all also zeroes g_cnt)
    conv_w_all<<<(163840 + 255) / 256, 256>>>(W2, W3, W4);
    count_kernel<<<(NE + 255) / 256, 256>>>(edst);
    scan1_kernel<<<SCAN_B, 256>>>();
    finalize_kernel<<<SCAN_B, 256>>>();
    fill_kernel<<<(NE + 255) / 256, 256>>>(esrc, edst);

    const int AGG_GRID = (NN + 7) / 8;
    dim3 ggrid(TM, 2);

    // layer 1: fused agg9 + GEMM(9->128) + relu -> g_h16 (stride 128)
    layer1_kernel<<<AGG_GRID, 256>>>(x, W1, b1);

    // layer 2: agg(F=128) -> fp16 A ; mma GEMM K=128 -> g_h16 (stride 256)
    agg_f16<128><<<AGG_GRID, 256>>>();
    gemm_mma<false><<<ggrid, 256, GT_SMEM>>>(b2, 1, 128, 0, batch);

    // layer 3
    agg_f16<256><<<AGG_GRID, 256>>>();
    gemm_mma<false><<<ggrid, 256, GT_SMEM>>>(b3, 1, 256, 1, batch);

    // layer 4: GEMM + fused segmented max-pool -> g_pool (no activation store)
    agg_f16<256><<<AGG_GRID, 256>>>();
    gemm_mma<true><<<ggrid, 256, GT_SMEM>>>(b4, 0, 256, 2, batch);

    // head
    head_kernel<<<NG, 128>>>(Wl2, bl2, Wl3, bl3, Wl, bl, out);
}